// round 7
// baseline (speedup 1.0000x reference)
#include <cuda_runtime.h>
#include <cuda_fp16.h>
#include <math.h>

#define MAX_NODE 200000
#define MAX_REL  401
#define DIM      64
#define NODE_STRIDE 96   // floats per node row: 64 fp32 x | 64 fp16 A (=32 float slots)

// Scratch:
//   node table: [expmap0(h): 64 fp32 | A=h@Ws: 64 fp16 PERMUTED] per node (~77 MB)
//     A permutation: uint4 slot p (bytes 256+16p) = columns {4p..4p+3, 32+4p..32+4p+3}
//   rel  table: [expmap0(r) 64 | B=r@Wr 64 | C=r@Wqr+b 64] fp32 per rel (~300 KB)
//   agg buffer: scatter-sum destination (~51 MB)
__device__ float d_nodeT[(size_t)MAX_NODE * NODE_STRIDE];
__device__ float d_relT[(size_t)MAX_REL * 192];
__device__ float d_agg[(size_t)MAX_NODE * 64];

// ---- packed fp32x2 helpers ------------------------------------------------
__device__ __forceinline__ unsigned long long pk2(float a, float b) {
    unsigned long long r;
    asm("mov.b64 %0, {%1, %2};" : "=l"(r) : "f"(a), "f"(b));
    return r;
}
__device__ __forceinline__ unsigned long long fma2(unsigned long long a,
                                                   unsigned long long b,
                                                   unsigned long long c) {
    unsigned long long d;
    asm("fma.rn.f32x2 %0, %1, %2, %3;" : "=l"(d) : "l"(a), "l"(b), "l"(c));
    return d;
}
__device__ __forceinline__ void upk2(unsigned long long v, float& lo, float& hi) {
    asm("mov.b64 {%0, %1}, %2;" : "=f"(lo), "=f"(hi) : "l"(v));
}

// ---------------------------------------------------------------------------
// K1: relation table. One warp per relation. Lane l owns dims 2l, 2l+1.
// ---------------------------------------------------------------------------
__global__ void build_rel(const float* __restrict__ rela,
                          const float* __restrict__ Wr,
                          const float* __restrict__ Wqr,
                          const float* __restrict__ Wqr_b,
                          const float* __restrict__ curv, int nRel) {
    __shared__ float sh[8][64];
    int warp = threadIdx.x >> 5, lane = threadIdx.x & 31;
    int r = blockIdx.x * 8 + warp;
    if (r >= nRel) return;
    float c = fmaxf(curv[0], 1e-6f);
    float sc = sqrtf(c);

    float2 h = ((const float2*)(rela + (size_t)r * 64))[lane];
    sh[warp][2 * lane] = h.x;
    sh[warp][2 * lane + 1] = h.y;

    float n2 = h.x * h.x + h.y * h.y;
#pragma unroll
    for (int off = 16; off; off >>= 1) n2 += __shfl_xor_sync(~0u, n2, off);
    float un = fmaxf(sqrtf(n2), 1e-15f);
    float arg = fminf(sc * un, 15.0f);
    float t = tanhf(arg);
    float gs = t / (sc * un);
    float gn = fmaxf(un * gs, 1e-15f);
    float maxn = 0.996f / sc;
    if (gn > maxn) gs *= maxn / gn;

    float2* orow = (float2*)(d_relT + (size_t)r * 192);
    orow[lane] = make_float2(h.x * gs, h.y * gs);
    __syncwarp();

    float b0 = 0.f, b1 = 0.f;
    float c0 = Wqr_b[2 * lane], c1 = Wqr_b[2 * lane + 1];
    for (int i = 0; i < 64; i++) {
        float hi = sh[warp][i];
        float2 wr = ((const float2*)(Wr + (size_t)i * 64))[lane];
        float2 wq = ((const float2*)(Wqr + (size_t)i * 64))[lane];
        b0 = fmaf(hi, wr.x, b0); b1 = fmaf(hi, wr.y, b1);
        c0 = fmaf(hi, wq.x, c0); c1 = fmaf(hi, wq.y, c1);
    }
    orow[32 + lane] = make_float2(b0, b1);
    orow[64 + lane] = make_float2(c0, c1);
}

// ---------------------------------------------------------------------------
// K2: node table + agg zeroing. 256 threads, 64 nodes per block.
// A = h@Ws via 4-node x 4-col f32x2 register tiles; fp16 PERMUTED store.
// ---------------------------------------------------------------------------
__global__ void __launch_bounds__(256)
build_node(const float* __restrict__ hidden,
           const float* __restrict__ Ws,
           const float* __restrict__ curv, int nNode) {
    __shared__ float sh[64][64];   // 16 KB
    int t = threadIdx.x;           // 0..255
    int base = blockIdx.x * 64;
    float c = fmaxf(curv[0], 1e-6f);
    float sc = sqrtf(c);

    // zero agg rows for these 64 nodes (1024 float4s, 4 per thread)
    float4 z = make_float4(0.f, 0.f, 0.f, 0.f);
#pragma unroll
    for (int i = t; i < 1024; i += 256) {
        int n = base + (i >> 4);
        if (n < nNode) ((float4*)(d_agg + (size_t)n * 64))[i & 15] = z;
    }

    // load 64 node rows (coalesced scalar loads, 16 per thread)
#pragma unroll
    for (int i = t; i < 4096; i += 256) {
        int n = base + (i >> 6);
        sh[i >> 6][i & 63] = (n < nNode) ? hidden[(size_t)n * 64 + (i & 63)] : 0.f;
    }
    __syncthreads();

    int c4 = (t & 15) * 4;   // output column base (0..60)
    int ng = (t >> 4) * 4;   // node base within 64-node tile (0..60)

    unsigned long long accA[4], accB[4];
#pragma unroll
    for (int j = 0; j < 4; j++) { accA[j] = pk2(0.f, 0.f); accB[j] = pk2(0.f, 0.f); }

    for (int ib = 0; ib < 64; ib += 4) {
        float4 w0 = *(const float4*)&Ws[(size_t)(ib + 0) * 64 + c4];
        float4 w1 = *(const float4*)&Ws[(size_t)(ib + 1) * 64 + c4];
        float4 w2 = *(const float4*)&Ws[(size_t)(ib + 2) * 64 + c4];
        float4 w3 = *(const float4*)&Ws[(size_t)(ib + 3) * 64 + c4];
        unsigned long long wA0 = pk2(w0.x, w0.y), wB0 = pk2(w0.z, w0.w);
        unsigned long long wA1 = pk2(w1.x, w1.y), wB1 = pk2(w1.z, w1.w);
        unsigned long long wA2 = pk2(w2.x, w2.y), wB2 = pk2(w2.z, w2.w);
        unsigned long long wA3 = pk2(w3.x, w3.y), wB3 = pk2(w3.z, w3.w);
#pragma unroll
        for (int j = 0; j < 4; j++) {
            float4 hv = *(const float4*)&sh[ng + j][ib];
            unsigned long long h0 = pk2(hv.x, hv.x);
            unsigned long long h1 = pk2(hv.y, hv.y);
            unsigned long long h2 = pk2(hv.z, hv.z);
            unsigned long long h3 = pk2(hv.w, hv.w);
            accA[j] = fma2(h0, wA0, accA[j]); accB[j] = fma2(h0, wB0, accB[j]);
            accA[j] = fma2(h1, wA1, accA[j]); accB[j] = fma2(h1, wB1, accB[j]);
            accA[j] = fma2(h2, wA2, accA[j]); accB[j] = fma2(h2, wB2, accB[j]);
            accA[j] = fma2(h3, wA3, accA[j]); accB[j] = fma2(h3, wB3, accB[j]);
        }
    }
    // Permuted fp16 store
    int a_off = (c4 < 32) ? (256 + 4 * c4) : (256 + 4 * (c4 - 32) + 8);
#pragma unroll
    for (int j = 0; j < 4; j++) {
        int n = base + ng + j;
        if (n < nNode) {
            float a0, a1, a2, a3;
            upk2(accA[j], a0, a1);
            upk2(accB[j], a2, a3);
            __half2 h01 = __floats2half2_rn(a0, a1);
            __half2 h23 = __floats2half2_rn(a2, a3);
            uint2 st;
            st.x = *(unsigned*)&h01;
            st.y = *(unsigned*)&h23;
            *(uint2*)((char*)(d_nodeT + (size_t)n * NODE_STRIDE) + a_off) = st;
        }
    }

    // expmap0: warp w handles nodes w, w+8, ... (8 nodes per warp)
    int warp = t >> 5, lane = t & 31;
    for (int k = warp; k < 64; k += 8) {
        int n = base + k;
        if (n >= nNode) continue;
        float h0 = sh[k][2 * lane], h1 = sh[k][2 * lane + 1];
        float n2 = h0 * h0 + h1 * h1;
#pragma unroll
        for (int off = 16; off; off >>= 1) n2 += __shfl_xor_sync(~0u, n2, off);
        float un = fmaxf(sqrtf(n2), 1e-15f);
        float arg = fminf(sc * un, 15.0f);
        float tt = tanhf(arg);
        float gs = tt / (sc * un);
        float gn = fmaxf(un * gs, 1e-15f);
        float maxn = 0.996f / sc;
        if (gn > maxn) gs *= maxn / gn;
        float2* orow = (float2*)(d_nodeT + (size_t)n * NODE_STRIDE);
        orow[lane] = make_float2(h0 * gs, h1 * gs);
    }
}

// ---------------------------------------------------------------------------
// K3: edge kernel. 4 edges per warp; 8 lanes per edge; lane owns the split
// dim set {4*l8.., 32+4*l8..}. Node gather: 2x float4 (x) + 1x uint4 (A fp16,
// permuted). Scatter: 2x red.global.add.v4.f32.
// ---------------------------------------------------------------------------
__global__ void __launch_bounds__(256)
edge_kernel(const int* __restrict__ sub, const int* __restrict__ rel,
            const int* __restrict__ obj, const int* __restrict__ qr,
            const float* __restrict__ walpha_w,
            const float* __restrict__ walpha_b,
            const float* __restrict__ curv, int E) {
    int lane = threadIdx.x & 31;
    int g    = lane >> 3;
    int l8   = lane & 7;
    int warpId = (blockIdx.x * blockDim.x + threadIdx.x) >> 5;
    long long e = (long long)warpId * 4 + g;
    bool valid = (e < E);
    int ei = valid ? (int)e : 0;

    float c = fmaxf(__ldg(curv), 1e-6f);
    float sc = sqrtf(c);

    int s = __ldg(sub + ei);
    int r = __ldg(rel + ei);
    int o = __ldg(obj + ei);
    int q = __ldg(qr + ei);

    const float* nbase = d_nodeT + (size_t)s * NODE_STRIDE;
    const float4* rrow = (const float4*)(d_relT + (size_t)r * 192);
    const float4* qrow = (const float4*)(d_relT + (size_t)q * 192);
    const float4* w4   = (const float4*)walpha_w;

    float4 x0 = ((const float4*)nbase)[l8];
    float4 x1 = ((const float4*)nbase)[8 + l8];
    uint4 araw = ((const uint4*)(nbase + 64))[l8];
    float4 y0 = rrow[l8],      y1 = rrow[8 + l8];
    float4 b0 = rrow[16 + l8], b1 = rrow[24 + l8];
    float4 c0 = qrow[32 + l8], c1 = qrow[40 + l8];
    float4 w0 = w4[l8],        w1 = w4[8 + l8];

    __half2* ah = (__half2*)&araw;
    float2 a01 = __half22float2(ah[0]);
    float2 a23 = __half22float2(ah[1]);
    float2 a45 = __half22float2(ah[2]);
    float2 a67 = __half22float2(ah[3]);

    float x2 = x0.x*x0.x + x0.y*x0.y + x0.z*x0.z + x0.w*x0.w
             + x1.x*x1.x + x1.y*x1.y + x1.z*x1.z + x1.w*x1.w;
    float y2 = y0.x*y0.x + y0.y*y0.y + y0.z*y0.z + y0.w*y0.w
             + y1.x*y1.x + y1.y*y1.y + y1.z*y1.z + y1.w*y1.w;
    float xy = x0.x*y0.x + x0.y*y0.y + x0.z*y0.z + x0.w*y0.w
             + x1.x*y1.x + x1.y*y1.y + x1.z*y1.z + x1.w*y1.w;
    float ap = fmaxf(a01.x + b0.x + c0.x, 0.f) * w0.x
             + fmaxf(a01.y + b0.y + c0.y, 0.f) * w0.y
             + fmaxf(a23.x + b0.z + c0.z, 0.f) * w0.z
             + fmaxf(a23.y + b0.w + c0.w, 0.f) * w0.w
             + fmaxf(a45.x + b1.x + c1.x, 0.f) * w1.x
             + fmaxf(a45.y + b1.y + c1.y, 0.f) * w1.y
             + fmaxf(a67.x + b1.z + c1.z, 0.f) * w1.z
             + fmaxf(a67.y + b1.w + c1.w, 0.f) * w1.w;

#pragma unroll
    for (int off = 4; off; off >>= 1) {
        x2 += __shfl_xor_sync(~0u, x2, off);
        y2 += __shfl_xor_sync(~0u, y2, off);
        xy += __shfl_xor_sync(~0u, xy, off);
        ap += __shfl_xor_sync(~0u, ap, off);
    }

    float ca = 1.f + 2.f * c * xy + c * y2;
    float cb = 1.f - c * x2;
    float den = fmaxf(1.f + 2.f * c * xy + c * c * x2 * y2, 1e-15f);
    float inv_den = 1.f / den;
    float m2 = ca * ca * x2 + 2.f * ca * cb * xy + cb * cb * y2;
    float mn = sqrtf(m2) * inv_den;

    float maxn = 0.996f / sc;
    float pscale = 1.f, nrm = mn;
    if (mn > maxn) { pscale = maxn / mn; nrm = maxn; }
    float yn = fmaxf(nrm, 1e-15f);
    float u = fminf(sc * yn, 1.f - 1e-5f);
    float art = 0.5f * __logf((1.f + u) / (1.f - u));
    float lf = art / (yn * sc);

    float alpha = 1.f / (1.f + __expf(-(ap + __ldg(walpha_b))));
    float coef = alpha * pscale * lf * inv_den;
    float va = ca * coef, vb = cb * coef;

    if (valid) {
        float* dst = d_agg + (size_t)o * 64 + 4 * l8;
        float p0 = va * x0.x + vb * y0.x;
        float p1 = va * x0.y + vb * y0.y;
        float p2 = va * x0.z + vb * y0.z;
        float p3 = va * x0.w + vb * y0.w;
        asm volatile("red.global.add.v4.f32 [%0], {%1, %2, %3, %4};"
                     :: "l"(dst), "f"(p0), "f"(p1), "f"(p2), "f"(p3) : "memory");
        float q0 = va * x1.x + vb * y1.x;
        float q1 = va * x1.y + vb * y1.y;
        float q2 = va * x1.z + vb * y1.z;
        float q3 = va * x1.w + vb * y1.w;
        asm volatile("red.global.add.v4.f32 [%0], {%1, %2, %3, %4};"
                     :: "l"(dst + 32), "f"(q0), "f"(q1), "f"(q2), "f"(q3) : "memory");
    }
}

// ---------------------------------------------------------------------------
// K4: out = agg @ Wh. 256 threads, 64 nodes per block, f32x2 register tiles.
// ---------------------------------------------------------------------------
__global__ void __launch_bounds__(256)
out_gemm(const float* __restrict__ Wh, float* __restrict__ out, int nNode) {
    __shared__ float sh[64][64];   // 16 KB
    int t = threadIdx.x;
    int base = blockIdx.x * 64;

#pragma unroll
    for (int i = t; i < 4096; i += 256) {
        int n = base + (i >> 6);
        sh[i >> 6][i & 63] = (n < nNode) ? d_agg[(size_t)n * 64 + (i & 63)] : 0.f;
    }
    __syncthreads();

    int c4 = (t & 15) * 4;
    int ng = (t >> 4) * 4;

    unsigned long long accA[4], accB[4];
#pragma unroll
    for (int j = 0; j < 4; j++) { accA[j] = pk2(0.f, 0.f); accB[j] = pk2(0.f, 0.f); }

    for (int ib = 0; ib < 64; ib += 4) {
        float4 w0 = *(const float4*)&Wh[(size_t)(ib + 0) * 64 + c4];
        float4 w1 = *(const float4*)&Wh[(size_t)(ib + 1) * 64 + c4];
        float4 w2 = *(const float4*)&Wh[(size_t)(ib + 2) * 64 + c4];
        float4 w3 = *(const float4*)&Wh[(size_t)(ib + 3) * 64 + c4];
        unsigned long long wA0 = pk2(w0.x, w0.y), wB0 = pk2(w0.z, w0.w);
        unsigned long long wA1 = pk2(w1.x, w1.y), wB1 = pk2(w1.z, w1.w);
        unsigned long long wA2 = pk2(w2.x, w2.y), wB2 = pk2(w2.z, w2.w);
        unsigned long long wA3 = pk2(w3.x, w3.y), wB3 = pk2(w3.z, w3.w);
#pragma unroll
        for (int j = 0; j < 4; j++) {
            float4 hv = *(const float4*)&sh[ng + j][ib];
            unsigned long long h0 = pk2(hv.x, hv.x);
            unsigned long long h1 = pk2(hv.y, hv.y);
            unsigned long long h2 = pk2(hv.z, hv.z);
            unsigned long long h3 = pk2(hv.w, hv.w);
            accA[j] = fma2(h0, wA0, accA[j]); accB[j] = fma2(h0, wB0, accB[j]);
            accA[j] = fma2(h1, wA1, accA[j]); accB[j] = fma2(h1, wB1, accB[j]);
            accA[j] = fma2(h2, wA2, accA[j]); accB[j] = fma2(h2, wB2, accB[j]);
            accA[j] = fma2(h3, wA3, accA[j]); accB[j] = fma2(h3, wB3, accB[j]);
        }
    }
#pragma unroll
    for (int j = 0; j < 4; j++) {
        int n = base + ng + j;
        if (n < nNode) {
            float4 o;
            upk2(accA[j], o.x, o.y);
            upk2(accB[j], o.z, o.w);
            *(float4*)&out[(size_t)n * 64 + c4] = o;
        }
    }
}

// ---------------------------------------------------------------------------
extern "C" void kernel_launch(void* const* d_in, const int* in_sizes, int n_in,
                              void* d_out, int out_size) {
    const float* hidden   = (const float*)d_in[0];
    const float* rela     = (const float*)d_in[1];
    const float* Ws       = (const float*)d_in[2];
    const float* Wr       = (const float*)d_in[3];
    const float* Wqr      = (const float*)d_in[4];
    const float* Wqr_b    = (const float*)d_in[5];
    const float* walpha_w = (const float*)d_in[6];
    const float* walpha_b = (const float*)d_in[7];
    const float* Wh       = (const float*)d_in[8];
    const float* curv     = (const float*)d_in[9];
    const int* sub = (const int*)d_in[10];
    const int* rel = (const int*)d_in[11];
    const int* obj = (const int*)d_in[12];
    const int* qr  = (const int*)d_in[13];
    float* out = (float*)d_out;

    int nNode = in_sizes[0] / DIM;
    int nRel  = in_sizes[1] / DIM;
    int E     = in_sizes[10];

    build_rel<<<(nRel + 7) / 8, 256>>>(rela, Wr, Wqr, Wqr_b, curv, nRel);
    build_node<<<(nNode + 63) / 64, 256>>>(hidden, Ws, curv, nNode);
    int blocks = (E + 31) / 32;   // 4 edges/warp, 8 warps/block
    edge_kernel<<<blocks, 256>>>(sub, rel, obj, qr, walpha_w, walpha_b, curv, E);
    out_gemm<<<(nNode + 63) / 64, 256>>>(Wh, out, nNode);
}

// round 8
// speedup vs baseline: 1.1036x; 1.1036x over previous
#include <cuda_runtime.h>
#include <cuda_fp16.h>
#include <math.h>

#define MAX_NODE 200000
#define MAX_REL  401
#define DIM      64
#define NODE_STRIDE 96   // floats per node row: 64 fp32 x | 64 fp16 A (=32 float slots)

// Scratch:
//   node table: [expmap0(h): 64 fp32 | A=h@Ws: 64 fp16 PERMUTED] per node (~77 MB)
//     A permutation: uint4 slot p (bytes 256+16p) = columns {4p..4p+3, 32+4p..32+4p+3}
//   rel  table: [expmap0(r) 64 | B=r@Wr 64 | C=r@Wqr+b 64] fp32 per rel (~300 KB)
//   agg buffer: scatter-sum destination (~51 MB)
__device__ float d_nodeT[(size_t)MAX_NODE * NODE_STRIDE];
__device__ float d_relT[(size_t)MAX_REL * 192];
__device__ float d_agg[(size_t)MAX_NODE * 64];

// ---- tf32 mma helpers -----------------------------------------------------
__device__ __forceinline__ unsigned tf32_rn(float f) {
    unsigned r;
    asm("cvt.rna.tf32.f32 %0, %1;" : "=r"(r) : "f"(f));
    return r;
}
__device__ __forceinline__ void mma_tf32(float d[4], const unsigned a[4], const unsigned b[2]) {
    asm("mma.sync.aligned.m16n8k8.row.col.f32.tf32.tf32.f32 "
        "{%0,%1,%2,%3}, {%4,%5,%6,%7}, {%8,%9}, {%0,%1,%2,%3};"
        : "+f"(d[0]), "+f"(d[1]), "+f"(d[2]), "+f"(d[3])
        : "r"(a[0]), "r"(a[1]), "r"(a[2]), "r"(a[3]), "r"(b[0]), "r"(b[1]));
}
// byte offset of fp16 A column j (even) inside the permuted node-row section
__device__ __forceinline__ int a_byte_off(int j) {
    return (j < 32) ? (256 + (j >> 2) * 16 + (j & 3) * 2)
                    : (256 + ((j - 32) >> 2) * 16 + 8 + ((j - 32) & 3) * 2);
}

// ---------------------------------------------------------------------------
// K1: relation table. One warp per relation. Lane l owns dims 2l, 2l+1.
// ---------------------------------------------------------------------------
__global__ void build_rel(const float* __restrict__ rela,
                          const float* __restrict__ Wr,
                          const float* __restrict__ Wqr,
                          const float* __restrict__ Wqr_b,
                          const float* __restrict__ curv, int nRel) {
    __shared__ float sh[8][64];
    int warp = threadIdx.x >> 5, lane = threadIdx.x & 31;
    int r = blockIdx.x * 8 + warp;
    if (r >= nRel) return;
    float c = fmaxf(curv[0], 1e-6f);
    float sc = sqrtf(c);

    float2 h = ((const float2*)(rela + (size_t)r * 64))[lane];
    sh[warp][2 * lane] = h.x;
    sh[warp][2 * lane + 1] = h.y;

    float n2 = h.x * h.x + h.y * h.y;
#pragma unroll
    for (int off = 16; off; off >>= 1) n2 += __shfl_xor_sync(~0u, n2, off);
    float un = fmaxf(sqrtf(n2), 1e-15f);
    float arg = fminf(sc * un, 15.0f);
    float t = tanhf(arg);
    float gs = t / (sc * un);
    float gn = fmaxf(un * gs, 1e-15f);
    float maxn = 0.996f / sc;
    if (gn > maxn) gs *= maxn / gn;

    float2* orow = (float2*)(d_relT + (size_t)r * 192);
    orow[lane] = make_float2(h.x * gs, h.y * gs);
    __syncwarp();

    float b0 = 0.f, b1 = 0.f;
    float c0 = Wqr_b[2 * lane], c1 = Wqr_b[2 * lane + 1];
    for (int i = 0; i < 64; i++) {
        float hi = sh[warp][i];
        float2 wr = ((const float2*)(Wr + (size_t)i * 64))[lane];
        float2 wq = ((const float2*)(Wqr + (size_t)i * 64))[lane];
        b0 = fmaf(hi, wr.x, b0); b1 = fmaf(hi, wr.y, b1);
        c0 = fmaf(hi, wq.x, c0); c1 = fmaf(hi, wq.y, c1);
    }
    orow[32 + lane] = make_float2(b0, b1);
    orow[64 + lane] = make_float2(c0, c1);
}

// ---------------------------------------------------------------------------
// K2: node table + agg zeroing. 128 threads (4 warps), 64 nodes per block.
// A = h@Ws via single-pass tf32 mma (result is fp16-quantized anyway).
// Warp w computes rows [16w,16w+16). fp16 PERMUTED store. expmap0 fp32.
// ---------------------------------------------------------------------------
__global__ void __launch_bounds__(128)
build_node(const float* __restrict__ hidden,
           const float* __restrict__ Ws,
           const float* __restrict__ curv, int nNode) {
    __shared__ float shA[64][68];   // padded: bank = (4*row + col) % 32
    __shared__ float shW[64][72];   // padded: bank = (8*k + n) % 32
    int t = threadIdx.x;            // 0..127
    int base = blockIdx.x * 64;
    float c = fmaxf(curv[0], 1e-6f);
    float sc = sqrtf(c);

    // zero agg rows for these 64 nodes (1024 float4 stores)
    float4 z = make_float4(0.f, 0.f, 0.f, 0.f);
#pragma unroll
    for (int i = t; i < 1024; i += 128) {
        int n = base + (i >> 4);
        if (n < nNode) ((float4*)(d_agg + (size_t)n * 64))[i & 15] = z;
    }
    // load Ws (64x64) and 64 hidden rows
#pragma unroll
    for (int i = t; i < 4096; i += 128) shW[i >> 6][i & 63] = Ws[i];
#pragma unroll
    for (int i = t; i < 4096; i += 128) {
        int rr = i >> 6, cc = i & 63;
        int n = base + rr;
        shA[rr][cc] = (n < nNode) ? hidden[(size_t)n * 64 + cc] : 0.f;
    }
    __syncthreads();

    int warp = t >> 5, lane = t & 31;
    int rowB = warp * 16;
    int qr = lane >> 2, tg = lane & 3;

    // A fragments (tf32), 8 k-steps
    unsigned av[8][4];
#pragma unroll
    for (int k = 0; k < 8; k++) {
        int col = k * 8 + tg;
        av[k][0] = tf32_rn(shA[rowB + qr][col]);
        av[k][1] = tf32_rn(shA[rowB + qr + 8][col]);
        av[k][2] = tf32_rn(shA[rowB + qr][col + 4]);
        av[k][3] = tf32_rn(shA[rowB + qr + 8][col + 4]);
    }

#pragma unroll
    for (int n8 = 0; n8 < 8; n8++) {
        float acc[4] = {0.f, 0.f, 0.f, 0.f};
#pragma unroll
        for (int k = 0; k < 8; k++) {
            unsigned bv[2];
            bv[0] = tf32_rn(shW[k * 8 + tg][n8 * 8 + qr]);
            bv[1] = tf32_rn(shW[k * 8 + tg + 4][n8 * 8 + qr]);
            mma_tf32(acc, av[k], bv);
        }
        int j = n8 * 8 + 2 * tg;            // even column
        int off = a_byte_off(j);
        int n0 = base + rowB + qr, n1 = n0 + 8;
        if (n0 < nNode) {
            __half2 hh = __floats2half2_rn(acc[0], acc[1]);
            *(__half2*)((char*)(d_nodeT + (size_t)n0 * NODE_STRIDE) + off) = hh;
        }
        if (n1 < nNode) {
            __half2 hh = __floats2half2_rn(acc[2], acc[3]);
            *(__half2*)((char*)(d_nodeT + (size_t)n1 * NODE_STRIDE) + off) = hh;
        }
    }

    // expmap0 per node; warp w handles nodes w, w+4, ... (16 per warp)
    for (int k = warp; k < 64; k += 4) {
        int n = base + k;
        if (n >= nNode) continue;
        float h0 = shA[k][2 * lane], h1 = shA[k][2 * lane + 1];
        float n2 = h0 * h0 + h1 * h1;
#pragma unroll
        for (int off = 16; off; off >>= 1) n2 += __shfl_xor_sync(~0u, n2, off);
        float un = fmaxf(sqrtf(n2), 1e-15f);
        float arg = fminf(sc * un, 15.0f);
        float tt = tanhf(arg);
        float gs = tt / (sc * un);
        float gn = fmaxf(un * gs, 1e-15f);
        float maxn = 0.996f / sc;
        if (gn > maxn) gs *= maxn / gn;
        float2* orow = (float2*)(d_nodeT + (size_t)n * NODE_STRIDE);
        orow[lane] = make_float2(h0 * gs, h1 * gs);
    }
}

// ---------------------------------------------------------------------------
// K3: edge kernel. 4 edges per warp; 8 lanes per edge; lane owns the split
// dim set {4*l8.., 32+4*l8..}. Scatter: 2x red.global.add.v4.f32. (unchanged)
// ---------------------------------------------------------------------------
__global__ void __launch_bounds__(256)
edge_kernel(const int* __restrict__ sub, const int* __restrict__ rel,
            const int* __restrict__ obj, const int* __restrict__ qr,
            const float* __restrict__ walpha_w,
            const float* __restrict__ walpha_b,
            const float* __restrict__ curv, int E) {
    int lane = threadIdx.x & 31;
    int g    = lane >> 3;
    int l8   = lane & 7;
    int warpId = (blockIdx.x * blockDim.x + threadIdx.x) >> 5;
    long long e = (long long)warpId * 4 + g;
    bool valid = (e < E);
    int ei = valid ? (int)e : 0;

    float c = fmaxf(__ldg(curv), 1e-6f);
    float sc = sqrtf(c);

    int s = __ldg(sub + ei);
    int r = __ldg(rel + ei);
    int o = __ldg(obj + ei);
    int q = __ldg(qr + ei);

    const float* nbase = d_nodeT + (size_t)s * NODE_STRIDE;
    const float4* rrow = (const float4*)(d_relT + (size_t)r * 192);
    const float4* qrow = (const float4*)(d_relT + (size_t)q * 192);
    const float4* w4   = (const float4*)walpha_w;

    float4 x0 = ((const float4*)nbase)[l8];
    float4 x1 = ((const float4*)nbase)[8 + l8];
    uint4 araw = ((const uint4*)(nbase + 64))[l8];
    float4 y0 = rrow[l8],      y1 = rrow[8 + l8];
    float4 b0 = rrow[16 + l8], b1 = rrow[24 + l8];
    float4 c0 = qrow[32 + l8], c1 = qrow[40 + l8];
    float4 w0 = w4[l8],        w1 = w4[8 + l8];

    __half2* ah = (__half2*)&araw;
    float2 a01 = __half22float2(ah[0]);
    float2 a23 = __half22float2(ah[1]);
    float2 a45 = __half22float2(ah[2]);
    float2 a67 = __half22float2(ah[3]);

    float x2 = x0.x*x0.x + x0.y*x0.y + x0.z*x0.z + x0.w*x0.w
             + x1.x*x1.x + x1.y*x1.y + x1.z*x1.z + x1.w*x1.w;
    float y2 = y0.x*y0.x + y0.y*y0.y + y0.z*y0.z + y0.w*y0.w
             + y1.x*y1.x + y1.y*y1.y + y1.z*y1.z + y1.w*y1.w;
    float xy = x0.x*y0.x + x0.y*y0.y + x0.z*y0.z + x0.w*y0.w
             + x1.x*y1.x + x1.y*y1.y + x1.z*y1.z + x1.w*y1.w;
    float ap = fmaxf(a01.x + b0.x + c0.x, 0.f) * w0.x
             + fmaxf(a01.y + b0.y + c0.y, 0.f) * w0.y
             + fmaxf(a23.x + b0.z + c0.z, 0.f) * w0.z
             + fmaxf(a23.y + b0.w + c0.w, 0.f) * w0.w
             + fmaxf(a45.x + b1.x + c1.x, 0.f) * w1.x
             + fmaxf(a45.y + b1.y + c1.y, 0.f) * w1.y
             + fmaxf(a67.x + b1.z + c1.z, 0.f) * w1.z
             + fmaxf(a67.y + b1.w + c1.w, 0.f) * w1.w;

#pragma unroll
    for (int off = 4; off; off >>= 1) {
        x2 += __shfl_xor_sync(~0u, x2, off);
        y2 += __shfl_xor_sync(~0u, y2, off);
        xy += __shfl_xor_sync(~0u, xy, off);
        ap += __shfl_xor_sync(~0u, ap, off);
    }

    float ca = 1.f + 2.f * c * xy + c * y2;
    float cb = 1.f - c * x2;
    float den = fmaxf(1.f + 2.f * c * xy + c * c * x2 * y2, 1e-15f);
    float inv_den = 1.f / den;
    float m2 = ca * ca * x2 + 2.f * ca * cb * xy + cb * cb * y2;
    float mn = sqrtf(m2) * inv_den;

    float maxn = 0.996f / sc;
    float pscale = 1.f, nrm = mn;
    if (mn > maxn) { pscale = maxn / mn; nrm = maxn; }
    float yn = fmaxf(nrm, 1e-15f);
    float u = fminf(sc * yn, 1.f - 1e-5f);
    float art = 0.5f * __logf((1.f + u) / (1.f - u));
    float lf = art / (yn * sc);

    float alpha = 1.f / (1.f + __expf(-(ap + __ldg(walpha_b))));
    float coef = alpha * pscale * lf * inv_den;
    float va = ca * coef, vb = cb * coef;

    if (valid) {
        float* dst = d_agg + (size_t)o * 64 + 4 * l8;
        float p0 = va * x0.x + vb * y0.x;
        float p1 = va * x0.y + vb * y0.y;
        float p2 = va * x0.z + vb * y0.z;
        float p3 = va * x0.w + vb * y0.w;
        asm volatile("red.global.add.v4.f32 [%0], {%1, %2, %3, %4};"
                     :: "l"(dst), "f"(p0), "f"(p1), "f"(p2), "f"(p3) : "memory");
        float q0 = va * x1.x + vb * y1.x;
        float q1 = va * x1.y + vb * y1.y;
        float q2 = va * x1.z + vb * y1.z;
        float q3 = va * x1.w + vb * y1.w;
        asm volatile("red.global.add.v4.f32 [%0], {%1, %2, %3, %4};"
                     :: "l"(dst + 32), "f"(q0), "f"(q1), "f"(q2), "f"(q3) : "memory");
    }
}

// ---------------------------------------------------------------------------
// K4: out = agg @ Wh via tf32 mma with 3-term error-corrected split
// (Ah*Wh + Ah*Wl + Al*Wh): ~fp32-accurate, tensor-pipe compute, DRAM-bound.
// 128 threads (4 warps), 64 rows per block; warp computes 16 rows x 64 cols.
// ---------------------------------------------------------------------------
__global__ void __launch_bounds__(128)
out_gemm(const float* __restrict__ Wh, float* __restrict__ out, int nNode) {
    __shared__ float shA[64][68];
    __shared__ float shW[64][72];
    int t = threadIdx.x;
    int base = blockIdx.x * 64;

#pragma unroll
    for (int i = t; i < 4096; i += 128) shW[i >> 6][i & 63] = Wh[i];
#pragma unroll
    for (int i = t; i < 4096; i += 128) {
        int rr = i >> 6, cc = i & 63;
        int n = base + rr;
        shA[rr][cc] = (n < nNode) ? d_agg[(size_t)n * 64 + cc] : 0.f;
    }
    __syncthreads();

    int warp = t >> 5, lane = t & 31;
    int rowB = warp * 16;
    int qr = lane >> 2, tg = lane & 3;

    // A fragments hi/lo for 8 k-steps
    unsigned ah4[8][4], al4[8][4];
#pragma unroll
    for (int k = 0; k < 8; k++) {
        int col = k * 8 + tg;
#pragma unroll
        for (int r = 0; r < 4; r++) {
            int row = rowB + qr + ((r & 1) ? 8 : 0);
            int cc = col + ((r >= 2) ? 4 : 0);
            float v = shA[row][cc];
            unsigned h = tf32_rn(v);
            ah4[k][r] = h;
            al4[k][r] = tf32_rn(v - __uint_as_float(h));
        }
    }

#pragma unroll
    for (int n8 = 0; n8 < 8; n8++) {
        float acc[4] = {0.f, 0.f, 0.f, 0.f};
#pragma unroll
        for (int k = 0; k < 8; k++) {
            float v0 = shW[k * 8 + tg][n8 * 8 + qr];
            float v1 = shW[k * 8 + tg + 4][n8 * 8 + qr];
            unsigned bh[2], bl[2];
            bh[0] = tf32_rn(v0);
            bh[1] = tf32_rn(v1);
            bl[0] = tf32_rn(v0 - __uint_as_float(bh[0]));
            bl[1] = tf32_rn(v1 - __uint_as_float(bh[1]));
            mma_tf32(acc, ah4[k], bh);
            mma_tf32(acc, al4[k], bh);
            mma_tf32(acc, ah4[k], bl);
        }
        int j = n8 * 8 + 2 * tg;
        int n0 = base + rowB + qr, n1 = n0 + 8;
        if (n0 < nNode) *(float2*)&out[(size_t)n0 * 64 + j] = make_float2(acc[0], acc[1]);
        if (n1 < nNode) *(float2*)&out[(size_t)n1 * 64 + j] = make_float2(acc[2], acc[3]);
    }
}

// ---------------------------------------------------------------------------
extern "C" void kernel_launch(void* const* d_in, const int* in_sizes, int n_in,
                              void* d_out, int out_size) {
    const float* hidden   = (const float*)d_in[0];
    const float* rela     = (const float*)d_in[1];
    const float* Ws       = (const float*)d_in[2];
    const float* Wr       = (const float*)d_in[3];
    const float* Wqr      = (const float*)d_in[4];
    const float* Wqr_b    = (const float*)d_in[5];
    const float* walpha_w = (const float*)d_in[6];
    const float* walpha_b = (const float*)d_in[7];
    const float* Wh       = (const float*)d_in[8];
    const float* curv     = (const float*)d_in[9];
    const int* sub = (const int*)d_in[10];
    const int* rel = (const int*)d_in[11];
    const int* obj = (const int*)d_in[12];
    const int* qr  = (const int*)d_in[13];
    float* out = (float*)d_out;

    int nNode = in_sizes[0] / DIM;
    int nRel  = in_sizes[1] / DIM;
    int E     = in_sizes[10];

    build_rel<<<(nRel + 7) / 8, 256>>>(rela, Wr, Wqr, Wqr_b, curv, nRel);
    build_node<<<(nNode + 63) / 64, 128>>>(hidden, Ws, curv, nNode);
    int blocks = (E + 31) / 32;   // 4 edges/warp, 8 warps/block
    edge_kernel<<<blocks, 256>>>(sub, rel, obj, qr, walpha_w, walpha_b, curv, E);
    out_gemm<<<(nNode + 63) / 64, 128>>>(Wh, out, nNode);
}

// round 11
// speedup vs baseline: 1.1053x; 1.0015x over previous
#include <cuda_runtime.h>
#include <cuda_fp16.h>
#include <math.h>

#define MAX_NODE 200000
#define MAX_REL  401
#define DIM      64
#define NODE_STRIDE 64   // floats per node row: 256B = [x fp16 64 | A fp16 64], permuted

// Scratch:
//   node table: [expmap0(h): 64 fp16 | A=h@Ws: 64 fp16], both PERMUTED (~51 MB)
//     permutation: 16B slot p of each section = dims {4p..4p+3, 32+4p..32+4p+3}
//   rel  table: [expmap0(r) 64 | B=r@Wr 64 | C=r@Wqr+b 64] fp32 per rel (~300 KB)
//   agg buffer: scatter-sum destination (~51 MB)
__device__ float d_nodeT[(size_t)MAX_NODE * NODE_STRIDE];
__device__ float d_relT[(size_t)MAX_REL * 192];
__device__ float d_agg[(size_t)MAX_NODE * 64];

// ---- tf32 mma helpers -----------------------------------------------------
__device__ __forceinline__ unsigned tf32_rn(float f) {
    unsigned r;
    asm("cvt.rna.tf32.f32 %0, %1;" : "=r"(r) : "f"(f));
    return r;
}
__device__ __forceinline__ void mma_tf32(float d[4], const unsigned a[4], const unsigned b[2]) {
    asm("mma.sync.aligned.m16n8k8.row.col.f32.tf32.tf32.f32 "
        "{%0,%1,%2,%3}, {%4,%5,%6,%7}, {%8,%9}, {%0,%1,%2,%3};"
        : "+f"(d[0]), "+f"(d[1]), "+f"(d[2]), "+f"(d[3])
        : "r"(a[0]), "r"(a[1]), "r"(a[2]), "r"(a[3]), "r"(b[0]), "r"(b[1]));
}
// byte offset of fp16 column j within a permuted 128B section (j even)
__device__ __forceinline__ int perm_off(int j) {
    return (j < 32) ? ((j >> 2) * 16 + (j & 3) * 2)
                    : (((j - 32) >> 2) * 16 + 8 + ((j - 32) & 3) * 2);
}

// ---------------------------------------------------------------------------
// K1: relation table. One warp per relation. Lane l owns dims 2l, 2l+1.
// ---------------------------------------------------------------------------
__global__ void build_rel(const float* __restrict__ rela,
                          const float* __restrict__ Wr,
                          const float* __restrict__ Wqr,
                          const float* __restrict__ Wqr_b,
                          const float* __restrict__ curv, int nRel) {
    __shared__ float sh[8][64];
    int warp = threadIdx.x >> 5, lane = threadIdx.x & 31;
    int r = blockIdx.x * 8 + warp;
    if (r >= nRel) return;
    float c = fmaxf(curv[0], 1e-6f);
    float sc = sqrtf(c);

    float2 h = ((const float2*)(rela + (size_t)r * 64))[lane];
    sh[warp][2 * lane] = h.x;
    sh[warp][2 * lane + 1] = h.y;

    float n2 = h.x * h.x + h.y * h.y;
#pragma unroll
    for (int off = 16; off; off >>= 1) n2 += __shfl_xor_sync(~0u, n2, off);
    float un = fmaxf(sqrtf(n2), 1e-15f);
    float arg = fminf(sc * un, 15.0f);
    float t = tanhf(arg);
    float gs = t / (sc * un);
    float gn = fmaxf(un * gs, 1e-15f);
    float maxn = 0.996f / sc;
    if (gn > maxn) gs *= maxn / gn;

    float2* orow = (float2*)(d_relT + (size_t)r * 192);
    orow[lane] = make_float2(h.x * gs, h.y * gs);
    __syncwarp();

    float b0 = 0.f, b1 = 0.f;
    float c0 = Wqr_b[2 * lane], c1 = Wqr_b[2 * lane + 1];
    for (int i = 0; i < 64; i++) {
        float hi = sh[warp][i];
        float2 wr = ((const float2*)(Wr + (size_t)i * 64))[lane];
        float2 wq = ((const float2*)(Wqr + (size_t)i * 64))[lane];
        b0 = fmaf(hi, wr.x, b0); b1 = fmaf(hi, wr.y, b1);
        c0 = fmaf(hi, wq.x, c0); c1 = fmaf(hi, wq.y, c1);
    }
    orow[32 + lane] = make_float2(b0, b1);
    orow[64 + lane] = make_float2(c0, c1);
}

// ---------------------------------------------------------------------------
// K2: node table + agg zeroing. 128 threads (4 warps), 64 nodes per block.
// A = h@Ws via single-pass tf32 mma (attention-path only). fp16 PERMUTED
// stores for both x (expmap0) and A sections.
// ---------------------------------------------------------------------------
__global__ void __launch_bounds__(128)
build_node(const float* __restrict__ hidden,
           const float* __restrict__ Ws,
           const float* __restrict__ curv, int nNode) {
    __shared__ float shA[64][68];   // hidden rows, pad 68 (conflict-free frags)
    __shared__ float shW[64][72];   // Ws, pad 72 (conflict-free frags)
    int t = threadIdx.x;            // 0..127
    int base = blockIdx.x * 64;
    float c = fmaxf(curv[0], 1e-6f);
    float sc = sqrtf(c);

    // zero agg rows for these 64 nodes
    float4 z = make_float4(0.f, 0.f, 0.f, 0.f);
#pragma unroll
    for (int i = t; i < 1024; i += 128) {
        int n = base + (i >> 4);
        if (n < nNode) ((float4*)(d_agg + (size_t)n * 64))[i & 15] = z;
    }
#pragma unroll
    for (int i = t; i < 4096; i += 128) shW[i >> 6][i & 63] = Ws[i];
#pragma unroll
    for (int i = t; i < 4096; i += 128) {
        int rr = i >> 6, cc = i & 63;
        int n = base + rr;
        shA[rr][cc] = (n < nNode) ? hidden[(size_t)n * 64 + cc] : 0.f;
    }
    __syncthreads();

    int warp = t >> 5, lane = t & 31;
    int rowB = warp * 16;
    int qr = lane >> 2, tg = lane & 3;

    unsigned av[8][4];
#pragma unroll
    for (int k = 0; k < 8; k++) {
        int col = k * 8 + tg;
        av[k][0] = tf32_rn(shA[rowB + qr][col]);
        av[k][1] = tf32_rn(shA[rowB + qr + 8][col]);
        av[k][2] = tf32_rn(shA[rowB + qr][col + 4]);
        av[k][3] = tf32_rn(shA[rowB + qr + 8][col + 4]);
    }

#pragma unroll
    for (int n8 = 0; n8 < 8; n8++) {
        float acc[4] = {0.f, 0.f, 0.f, 0.f};
#pragma unroll
        for (int k = 0; k < 8; k++) {
            unsigned bv[2];
            bv[0] = tf32_rn(shW[k * 8 + tg][n8 * 8 + qr]);
            bv[1] = tf32_rn(shW[k * 8 + tg + 4][n8 * 8 + qr]);
            mma_tf32(acc, av[k], bv);
        }
        int j = n8 * 8 + 2 * tg;                   // even column
        int off = 128 + perm_off(j);               // A section at byte 128
        int n0 = base + rowB + qr, n1 = n0 + 8;
        if (n0 < nNode) {
            __half2 hh = __floats2half2_rn(acc[0], acc[1]);
            *(__half2*)((char*)(d_nodeT + (size_t)n0 * NODE_STRIDE) + off) = hh;
        }
        if (n1 < nNode) {
            __half2 hh = __floats2half2_rn(acc[2], acc[3]);
            *(__half2*)((char*)(d_nodeT + (size_t)n1 * NODE_STRIDE) + off) = hh;
        }
    }

    // expmap0 per node (fp32 math, fp16 permuted store); warp w: nodes w, w+4, ...
    for (int k = warp; k < 64; k += 4) {
        int n = base + k;
        if (n >= nNode) continue;
        float h0 = shA[k][2 * lane], h1 = shA[k][2 * lane + 1];
        float n2 = h0 * h0 + h1 * h1;
#pragma unroll
        for (int off = 16; off; off >>= 1) n2 += __shfl_xor_sync(~0u, n2, off);
        float un = fmaxf(sqrtf(n2), 1e-15f);
        float arg = fminf(sc * un, 15.0f);
        float tt = tanhf(arg);
        float gs = tt / (sc * un);
        float gn = fmaxf(un * gs, 1e-15f);
        float maxn = 0.996f / sc;
        if (gn > maxn) gs *= maxn / gn;
        int off = perm_off(2 * lane);              // x section at byte 0
        __half2 hh = __floats2half2_rn(h0 * gs, h1 * gs);
        *(__half2*)((char*)(d_nodeT + (size_t)n * NODE_STRIDE) + off) = hh;
    }
}

// ---------------------------------------------------------------------------
// K3: edge kernel. 4 edges per warp; 8 lanes per edge; lane owns the split
// dim set {4*l8.., 32+4*l8..}. Node gather: 2x uint4 (x fp16 + A fp16).
// Scatter: 2x red.global.add.v4.f32 into fp32 agg.
// ---------------------------------------------------------------------------
__global__ void __launch_bounds__(256)
edge_kernel(const int* __restrict__ sub, const int* __restrict__ rel,
            const int* __restrict__ obj, const int* __restrict__ qr,
            const float* __restrict__ walpha_w,
            const float* __restrict__ walpha_b,
            const float* __restrict__ curv, int E) {
    int lane = threadIdx.x & 31;
    int g    = lane >> 3;
    int l8   = lane & 7;
    int warpId = (blockIdx.x * blockDim.x + threadIdx.x) >> 5;
    long long e = (long long)warpId * 4 + g;
    bool valid = (e < E);
    int ei = valid ? (int)e : 0;

    float c = fmaxf(__ldg(curv), 1e-6f);
    float sc = sqrtf(c);

    int s = __ldg(sub + ei);
    int r = __ldg(rel + ei);
    int o = __ldg(obj + ei);
    int q = __ldg(qr + ei);

    const uint4* nrow = (const uint4*)(d_nodeT + (size_t)s * NODE_STRIDE);
    const float4* rrow = (const float4*)(d_relT + (size_t)r * 192);
    const float4* qrow = (const float4*)(d_relT + (size_t)q * 192);
    const float4* w4   = (const float4*)walpha_w;

    uint4 xraw = nrow[l8];        // x dims {4l8.., 32+4l8..} as 8 fp16
    uint4 araw = nrow[8 + l8];    // A dims, same split set
    float4 y0 = rrow[l8],      y1 = rrow[8 + l8];
    float4 b0 = rrow[16 + l8], b1 = rrow[24 + l8];
    float4 c0 = qrow[32 + l8], c1 = qrow[40 + l8];
    float4 w0 = w4[l8],        w1 = w4[8 + l8];

    __half2* xh = (__half2*)&xraw;
    float2 x01 = __half22float2(xh[0]);
    float2 x23 = __half22float2(xh[1]);
    float2 x45 = __half22float2(xh[2]);
    float2 x67 = __half22float2(xh[3]);
    float4 x0 = make_float4(x01.x, x01.y, x23.x, x23.y);
    float4 x1 = make_float4(x45.x, x45.y, x67.x, x67.y);

    __half2* ah = (__half2*)&araw;
    float2 a01 = __half22float2(ah[0]);
    float2 a23 = __half22float2(ah[1]);
    float2 a45 = __half22float2(ah[2]);
    float2 a67 = __half22float2(ah[3]);

    float x2 = x0.x*x0.x + x0.y*x0.y + x0.z*x0.z + x0.w*x0.w
             + x1.x*x1.x + x1.y*x1.y + x1.z*x1.z + x1.w*x1.w;
    float y2 = y0.x*y0.x + y0.y*y0.y + y0.z*y0.z + y0.w*y0.w
             + y1.x*y1.x + y1.y*y1.y + y1.z*y1.z + y1.w*y1.w;
    float xy = x0.x*y0.x + x0.y*y0.y + x0.z*y0.z + x0.w*y0.w
             + x1.x*y1.x + x1.y*y1.y + x1.z*y1.z + x1.w*y1.w;
    float ap = fmaxf(a01.x + b0.x + c0.x, 0.f) * w0.x
             + fmaxf(a01.y + b0.y + c0.y, 0.f) * w0.y
             + fmaxf(a23.x + b0.z + c0.z, 0.f) * w0.z
             + fmaxf(a23.y + b0.w + c0.w, 0.f) * w0.w
             + fmaxf(a45.x + b1.x + c1.x, 0.f) * w1.x
             + fmaxf(a45.y + b1.y + c1.y, 0.f) * w1.y
             + fmaxf(a67.x + b1.z + c1.z, 0.f) * w1.z
             + fmaxf(a67.y + b1.w + c1.w, 0.f) * w1.w;

#pragma unroll
    for (int off = 4; off; off >>= 1) {
        x2 += __shfl_xor_sync(~0u, x2, off);
        y2 += __shfl_xor_sync(~0u, y2, off);
        xy += __shfl_xor_sync(~0u, xy, off);
        ap += __shfl_xor_sync(~0u, ap, off);
    }

    float ca = 1.f + 2.f * c * xy + c * y2;
    float cb = 1.f - c * x2;
    float den = fmaxf(1.f + 2.f * c * xy + c * c * x2 * y2, 1e-15f);
    float inv_den = 1.f / den;
    float m2 = ca * ca * x2 + 2.f * ca * cb * xy + cb * cb * y2;
    float mn = sqrtf(m2) * inv_den;

    float maxn = 0.996f / sc;
    float pscale = 1.f, nrm = mn;
    if (mn > maxn) { pscale = maxn / mn; nrm = maxn; }
    float yn = fmaxf(nrm, 1e-15f);
    float u = fminf(sc * yn, 1.f - 1e-5f);
    float art = 0.5f * __logf((1.f + u) / (1.f - u));
    float lf = art / (yn * sc);

    float alpha = 1.f / (1.f + __expf(-(ap + __ldg(walpha_b))));
    float coef = alpha * pscale * lf * inv_den;
    float va = ca * coef, vb = cb * coef;

    if (valid) {
        float* dst = d_agg + (size_t)o * 64 + 4 * l8;
        float p0 = va * x0.x + vb * y0.x;
        float p1 = va * x0.y + vb * y0.y;
        float p2 = va * x0.z + vb * y0.z;
        float p3 = va * x0.w + vb * y0.w;
        asm volatile("red.global.add.v4.f32 [%0], {%1, %2, %3, %4};"
                     :: "l"(dst), "f"(p0), "f"(p1), "f"(p2), "f"(p3) : "memory");
        float q0 = va * x1.x + vb * y1.x;
        float q1 = va * x1.y + vb * y1.y;
        float q2 = va * x1.z + vb * y1.z;
        float q3 = va * x1.w + vb * y1.w;
        asm volatile("red.global.add.v4.f32 [%0], {%1, %2, %3, %4};"
                     :: "l"(dst + 32), "f"(q0), "f"(q1), "f"(q2), "f"(q3) : "memory");
    }
}

// ---------------------------------------------------------------------------
// K4: out = agg @ Wh via tf32 3-term split (round-8 version: static smem,
// hi/lo A fragments hoisted in registers, B split in-loop).
// 128 threads (4 warps), 64 rows per block; warp computes 16 rows x 64 cols.
// ---------------------------------------------------------------------------
__global__ void __launch_bounds__(128)
out_gemm(const float* __restrict__ Wh, float* __restrict__ out, int nNode) {
    __shared__ float shA[64][68];
    __shared__ float shW[64][72];
    int t = threadIdx.x;
    int base = blockIdx.x * 64;

#pragma unroll
    for (int i = t; i < 4096; i += 128) shW[i >> 6][i & 63] = Wh[i];
#pragma unroll
    for (int i = t; i < 4096; i += 128) {
        int rr = i >> 6, cc = i & 63;
        int n = base + rr;
        shA[rr][cc] = (n < nNode) ? d_agg[(size_t)n * 64 + cc] : 0.f;
    }
    __syncthreads();

    int warp = t >> 5, lane = t & 31;
    int rowB = warp * 16;
    int qr = lane >> 2, tg = lane & 3;

    unsigned ah4[8][4], al4[8][4];
#pragma unroll
    for (int k = 0; k < 8; k++) {
        int col = k * 8 + tg;
#pragma unroll
        for (int r = 0; r < 4; r++) {
            int row = rowB + qr + ((r & 1) ? 8 : 0);
            int cc = col + ((r >= 2) ? 4 : 0);
            float v = shA[row][cc];
            unsigned h = tf32_rn(v);
            ah4[k][r] = h;
            al4[k][r] = tf32_rn(v - __uint_as_float(h));
        }
    }

#pragma unroll
    for (int n8 = 0; n8 < 8; n8++) {
        float acc[4] = {0.f, 0.f, 0.f, 0.f};
#pragma unroll
        for (int k = 0; k < 8; k++) {
            float v0 = shW[k * 8 + tg][n8 * 8 + qr];
            float v1 = shW[k * 8 + tg + 4][n8 * 8 + qr];
            unsigned bh[2], bl[2];
            bh[0] = tf32_rn(v0);
            bh[1] = tf32_rn(v1);
            bl[0] = tf32_rn(v0 - __uint_as_float(bh[0]));
            bl[1] = tf32_rn(v1 - __uint_as_float(bh[1]));
            mma_tf32(acc, ah4[k], bh);
            mma_tf32(acc, al4[k], bh);
            mma_tf32(acc, ah4[k], bl);
        }
        int j = n8 * 8 + 2 * tg;
        int n0 = base + rowB + qr, n1 = n0 + 8;
        if (n0 < nNode) *(float2*)&out[(size_t)n0 * 64 + j] = make_float2(acc[0], acc[1]);
        if (n1 < nNode) *(float2*)&out[(size_t)n1 * 64 + j] = make_float2(acc[2], acc[3]);
    }
}

// ---------------------------------------------------------------------------
extern "C" void kernel_launch(void* const* d_in, const int* in_sizes, int n_in,
                              void* d_out, int out_size) {
    const float* hidden   = (const float*)d_in[0];
    const float* rela     = (const float*)d_in[1];
    const float* Ws       = (const float*)d_in[2];
    const float* Wr       = (const float*)d_in[3];
    const float* Wqr      = (const float*)d_in[4];
    const float* Wqr_b    = (const float*)d_in[5];
    const float* walpha_w = (const float*)d_in[6];
    const float* walpha_b = (const float*)d_in[7];
    const float* Wh       = (const float*)d_in[8];
    const float* curv     = (const float*)d_in[9];
    const int* sub = (const int*)d_in[10];
    const int* rel = (const int*)d_in[11];
    const int* obj = (const int*)d_in[12];
    const int* qr  = (const int*)d_in[13];
    float* out = (float*)d_out;

    int nNode = in_sizes[0] / DIM;
    int nRel  = in_sizes[1] / DIM;
    int E     = in_sizes[10];

    build_rel<<<(nRel + 7) / 8, 256>>>(rela, Wr, Wqr, Wqr_b, curv, nRel);
    build_node<<<(nNode + 63) / 64, 128>>>(hidden, Ws, curv, nNode);
    int blocks = (E + 31) / 32;   // 4 edges/warp, 8 warps/block
    edge_kernel<<<blocks, 256>>>(sub, rel, obj, qr, walpha_w, walpha_b, curv, E);
    out_gemm<<<(nNode + 63) / 64, 128>>>(Wh, out, nNode);
}

// round 14
// speedup vs baseline: 1.2441x; 1.1256x over previous
#include <cuda_runtime.h>
#include <cuda_fp16.h>
#include <math.h>

#define MAX_NODE 200000
#define MAX_REL  401
#define DIM      64
#define NODE_STRIDE 64   // floats per node row: 256B = [x fp16 64 | A fp16 64], permuted
#define REL_STRIDE  96   // floats per rel row: 384B = [y fp16 | B fp16 | C fp16], permuted

// Scratch:
//   node table: [expmap0(h): 64 fp16 | A=h@Ws: 64 fp16], both PERMUTED (~51 MB)
//     permutation: 16B slot p of a section = dims {4p..4p+3, 32+4p..32+4p+3}
//   rel  table: [expmap0(r) | r@Wr | r@Wqr+b], fp16, same permuted slots (~150 KB)
//   agg buffer: scatter-sum destination fp32 (~51 MB)
__device__ float d_nodeT[(size_t)MAX_NODE * NODE_STRIDE];
__device__ float d_relT[(size_t)MAX_REL * REL_STRIDE];
__device__ float d_agg[(size_t)MAX_NODE * 64];

// ---- tf32 mma helpers -----------------------------------------------------
__device__ __forceinline__ unsigned tf32_rn(float f) {
    unsigned r;
    asm("cvt.rna.tf32.f32 %0, %1;" : "=r"(r) : "f"(f));
    return r;
}
__device__ __forceinline__ void mma_tf32(float d[4], const unsigned a[4], const unsigned b[2]) {
    asm("mma.sync.aligned.m16n8k8.row.col.f32.tf32.tf32.f32 "
        "{%0,%1,%2,%3}, {%4,%5,%6,%7}, {%8,%9}, {%0,%1,%2,%3};"
        : "+f"(d[0]), "+f"(d[1]), "+f"(d[2]), "+f"(d[3])
        : "r"(a[0]), "r"(a[1]), "r"(a[2]), "r"(a[3]), "r"(b[0]), "r"(b[1]));
}
// byte offset of fp16 column j within a permuted 128B section (j even)
__device__ __forceinline__ int perm_off(int j) {
    return (j < 32) ? ((j >> 2) * 16 + (j & 3) * 2)
                    : (((j - 32) >> 2) * 16 + 8 + ((j - 32) & 3) * 2);
}
// unpack a 16B slot (8 fp16) into two float4s (first/second half of slot)
__device__ __forceinline__ void unp8(uint4 u, float4& lo, float4& hi) {
    __half2* h = (__half2*)&u;
    float2 p0 = __half22float2(h[0]);
    float2 p1 = __half22float2(h[1]);
    float2 p2 = __half22float2(h[2]);
    float2 p3 = __half22float2(h[3]);
    lo = make_float4(p0.x, p0.y, p1.x, p1.y);
    hi = make_float4(p2.x, p2.y, p3.x, p3.y);
}
__device__ __forceinline__ float dot4(float4 a, float4 b) {
    return a.x * b.x + a.y * b.y + a.z * b.z + a.w * b.w;
}

// ---------------------------------------------------------------------------
// K1: relation table (fp16 permuted). One warp per relation; lane l owns
// dims 2l, 2l+1.
// ---------------------------------------------------------------------------
__global__ void build_rel(const float* __restrict__ rela,
                          const float* __restrict__ Wr,
                          const float* __restrict__ Wqr,
                          const float* __restrict__ Wqr_b,
                          const float* __restrict__ curv, int nRel) {
    __shared__ float sh[8][64];
    int warp = threadIdx.x >> 5, lane = threadIdx.x & 31;
    int r = blockIdx.x * 8 + warp;
    if (r >= nRel) return;
    float c = fmaxf(curv[0], 1e-6f);
    float sc = sqrtf(c);

    float2 h = ((const float2*)(rela + (size_t)r * 64))[lane];
    sh[warp][2 * lane] = h.x;
    sh[warp][2 * lane + 1] = h.y;

    float n2 = h.x * h.x + h.y * h.y;
#pragma unroll
    for (int off = 16; off; off >>= 1) n2 += __shfl_xor_sync(~0u, n2, off);
    float un = fmaxf(sqrtf(n2), 1e-15f);
    float arg = fminf(sc * un, 15.0f);
    float t = tanhf(arg);
    float gs = t / (sc * un);
    float gn = fmaxf(un * gs, 1e-15f);
    float maxn = 0.996f / sc;
    if (gn > maxn) gs *= maxn / gn;
    __syncwarp();

    float b0 = 0.f, b1 = 0.f;
    float c0 = Wqr_b[2 * lane], c1 = Wqr_b[2 * lane + 1];
    for (int i = 0; i < 64; i++) {
        float hi = sh[warp][i];
        float2 wr = ((const float2*)(Wr + (size_t)i * 64))[lane];
        float2 wq = ((const float2*)(Wqr + (size_t)i * 64))[lane];
        b0 = fmaf(hi, wr.x, b0); b1 = fmaf(hi, wr.y, b1);
        c0 = fmaf(hi, wq.x, c0); c1 = fmaf(hi, wq.y, c1);
    }
    char* base = (char*)(d_relT + (size_t)r * REL_STRIDE);
    int off = perm_off(2 * lane);
    *(__half2*)(base + off)       = __floats2half2_rn(h.x * gs, h.y * gs);
    *(__half2*)(base + 128 + off) = __floats2half2_rn(b0, b1);
    *(__half2*)(base + 256 + off) = __floats2half2_rn(c0, c1);
}

// ---------------------------------------------------------------------------
// K2: node table + agg zeroing. 128 threads (4 warps), 64 nodes per block.
// A = h@Ws via single-pass tf32 mma (attention-path only). fp16 PERMUTED
// stores for both x (expmap0) and A sections.
// ---------------------------------------------------------------------------
__global__ void __launch_bounds__(128)
build_node(const float* __restrict__ hidden,
           const float* __restrict__ Ws,
           const float* __restrict__ curv, int nNode) {
    __shared__ float shA[64][68];   // hidden rows, pad 68
    __shared__ float shW[64][72];   // Ws, pad 72
    int t = threadIdx.x;            // 0..127
    int base = blockIdx.x * 64;
    float c = fmaxf(curv[0], 1e-6f);
    float sc = sqrtf(c);

    // zero agg rows for these 64 nodes
    float4 z = make_float4(0.f, 0.f, 0.f, 0.f);
#pragma unroll
    for (int i = t; i < 1024; i += 128) {
        int n = base + (i >> 4);
        if (n < nNode) ((float4*)(d_agg + (size_t)n * 64))[i & 15] = z;
    }
#pragma unroll
    for (int i = t; i < 4096; i += 128) shW[i >> 6][i & 63] = Ws[i];
#pragma unroll
    for (int i = t; i < 4096; i += 128) {
        int rr = i >> 6, cc = i & 63;
        int n = base + rr;
        shA[rr][cc] = (n < nNode) ? hidden[(size_t)n * 64 + cc] : 0.f;
    }
    __syncthreads();

    int warp = t >> 5, lane = t & 31;
    int rowB = warp * 16;
    int qr = lane >> 2, tg = lane & 3;

    unsigned av[8][4];
#pragma unroll
    for (int k = 0; k < 8; k++) {
        int col = k * 8 + tg;
        av[k][0] = tf32_rn(shA[rowB + qr][col]);
        av[k][1] = tf32_rn(shA[rowB + qr + 8][col]);
        av[k][2] = tf32_rn(shA[rowB + qr][col + 4]);
        av[k][3] = tf32_rn(shA[rowB + qr + 8][col + 4]);
    }

#pragma unroll
    for (int n8 = 0; n8 < 8; n8++) {
        float acc[4] = {0.f, 0.f, 0.f, 0.f};
#pragma unroll
        for (int k = 0; k < 8; k++) {
            unsigned bv[2];
            bv[0] = tf32_rn(shW[k * 8 + tg][n8 * 8 + qr]);
            bv[1] = tf32_rn(shW[k * 8 + tg + 4][n8 * 8 + qr]);
            mma_tf32(acc, av[k], bv);
        }
        int j = n8 * 8 + 2 * tg;                   // even column
        int off = 128 + perm_off(j);               // A section at byte 128
        int n0 = base + rowB + qr, n1 = n0 + 8;
        if (n0 < nNode) {
            __half2 hh = __floats2half2_rn(acc[0], acc[1]);
            *(__half2*)((char*)(d_nodeT + (size_t)n0 * NODE_STRIDE) + off) = hh;
        }
        if (n1 < nNode) {
            __half2 hh = __floats2half2_rn(acc[2], acc[3]);
            *(__half2*)((char*)(d_nodeT + (size_t)n1 * NODE_STRIDE) + off) = hh;
        }
    }

    // expmap0 per node (fp32 math, fp16 permuted store); warp w: nodes w, w+4, ...
    for (int k = warp; k < 64; k += 4) {
        int n = base + k;
        if (n >= nNode) continue;
        float h0 = shA[k][2 * lane], h1 = shA[k][2 * lane + 1];
        float n2 = h0 * h0 + h1 * h1;
#pragma unroll
        for (int off = 16; off; off >>= 1) n2 += __shfl_xor_sync(~0u, n2, off);
        float un = fmaxf(sqrtf(n2), 1e-15f);
        float arg = fminf(sc * un, 15.0f);
        float tt = tanhf(arg);
        float gs = tt / (sc * un);
        float gn = fmaxf(un * gs, 1e-15f);
        float maxn = 0.996f / sc;
        if (gn > maxn) gs *= maxn / gn;
        int off = perm_off(2 * lane);              // x section at byte 0
        __half2 hh = __floats2half2_rn(h0 * gs, h1 * gs);
        *(__half2*)((char*)(d_nodeT + (size_t)n * NODE_STRIDE) + off) = hh;
    }
}

// ---------------------------------------------------------------------------
// K3: edge kernel. 8 edges per warp; 4 lanes per edge; lane owns slots
// {l4, l4+4} = dims {4l4.., 32+4l4.., 16+4l4.., 48+4l4..} (16 dims).
// All tables fp16 permuted. MIO ops per edge: ~3.25 (vs 6 before).
// Scatter: 4x red.global.add.v4.f32.
// ---------------------------------------------------------------------------
__global__ void __launch_bounds__(256)
edge_kernel(const int* __restrict__ sub, const int* __restrict__ rel,
            const int* __restrict__ obj, const int* __restrict__ qr,
            const float* __restrict__ walpha_w,
            const float* __restrict__ walpha_b,
            const float* __restrict__ curv, int E) {
    int lane = threadIdx.x & 31;
    int g    = lane >> 2;   // edge group 0..7
    int l4   = lane & 3;    // lane within 4-lane edge group
    int warpId = (blockIdx.x * blockDim.x + threadIdx.x) >> 5;
    long long e = (long long)warpId * 8 + g;
    bool valid = (e < E);
    int ei = valid ? (int)e : 0;

    float c = fmaxf(__ldg(curv), 1e-6f);
    float sc = sqrtf(c);

    int s = __ldg(sub + ei);
    int r = __ldg(rel + ei);
    int o = __ldg(obj + ei);
    int q = __ldg(qr + ei);

    const uint4* nrow = (const uint4*)(d_nodeT + (size_t)s * NODE_STRIDE);
    const uint4* rrow = (const uint4*)(d_relT + (size_t)r * REL_STRIDE);
    const uint4* qrow = (const uint4*)(d_relT + (size_t)q * REL_STRIDE);
    const float4* w4  = (const float4*)walpha_w;

    uint4 xu0 = nrow[l4],      xu1 = nrow[4 + l4];    // x slots l4, l4+4
    uint4 au0 = nrow[8 + l4],  au1 = nrow[12 + l4];   // A slots
    uint4 yu0 = rrow[l4],      yu1 = rrow[4 + l4];    // y slots
    uint4 bu0 = rrow[8 + l4],  bu1 = rrow[12 + l4];   // B slots
    uint4 cu0 = qrow[16 + l4], cu1 = qrow[20 + l4];   // C slots
    float4 wA0 = w4[l4],       wA1 = w4[8 + l4];      // w dims of slot l4
    float4 wB0 = w4[4 + l4],   wB1 = w4[12 + l4];     // w dims of slot l4+4

    float4 x0a, x0b, x1a, x1b, y0a, y0b, y1a, y1b;
    unp8(xu0, x0a, x0b); unp8(xu1, x1a, x1b);
    unp8(yu0, y0a, y0b); unp8(yu1, y1a, y1b);

    float x2 = dot4(x0a, x0a) + dot4(x0b, x0b) + dot4(x1a, x1a) + dot4(x1b, x1b);
    float y2 = dot4(y0a, y0a) + dot4(y0b, y0b) + dot4(y1a, y1a) + dot4(y1b, y1b);
    float xy = dot4(x0a, y0a) + dot4(x0b, y0b) + dot4(x1a, y1a) + dot4(x1b, y1b);

    float ap;
    {
        float4 aa, ab, ba, bb, ca, cb;
        unp8(au0, aa, ab); unp8(bu0, ba, bb); unp8(cu0, ca, cb);
        ap = fmaxf(aa.x + ba.x + ca.x, 0.f) * wA0.x
           + fmaxf(aa.y + ba.y + ca.y, 0.f) * wA0.y
           + fmaxf(aa.z + ba.z + ca.z, 0.f) * wA0.z
           + fmaxf(aa.w + ba.w + ca.w, 0.f) * wA0.w
           + fmaxf(ab.x + bb.x + cb.x, 0.f) * wA1.x
           + fmaxf(ab.y + bb.y + cb.y, 0.f) * wA1.y
           + fmaxf(ab.z + bb.z + cb.z, 0.f) * wA1.z
           + fmaxf(ab.w + bb.w + cb.w, 0.f) * wA1.w;
        unp8(au1, aa, ab); unp8(bu1, ba, bb); unp8(cu1, ca, cb);
        ap += fmaxf(aa.x + ba.x + ca.x, 0.f) * wB0.x
            + fmaxf(aa.y + ba.y + ca.y, 0.f) * wB0.y
            + fmaxf(aa.z + ba.z + ca.z, 0.f) * wB0.z
            + fmaxf(aa.w + ba.w + ca.w, 0.f) * wB0.w
            + fmaxf(ab.x + bb.x + cb.x, 0.f) * wB1.x
            + fmaxf(ab.y + bb.y + cb.y, 0.f) * wB1.y
            + fmaxf(ab.z + bb.z + cb.z, 0.f) * wB1.z
            + fmaxf(ab.w + bb.w + cb.w, 0.f) * wB1.w;
    }

    // reduce within the 4-lane group (xor offsets 2,1 stay inside group)
#pragma unroll
    for (int off = 2; off; off >>= 1) {
        x2 += __shfl_xor_sync(~0u, x2, off);
        y2 += __shfl_xor_sync(~0u, y2, off);
        xy += __shfl_xor_sync(~0u, xy, off);
        ap += __shfl_xor_sync(~0u, ap, off);
    }

    float ca = 1.f + 2.f * c * xy + c * y2;
    float cb = 1.f - c * x2;
    float den = fmaxf(1.f + 2.f * c * xy + c * c * x2 * y2, 1e-15f);
    float inv_den = 1.f / den;
    float m2 = ca * ca * x2 + 2.f * ca * cb * xy + cb * cb * y2;
    float mn = sqrtf(m2) * inv_den;

    float maxn = 0.996f / sc;
    float pscale = 1.f, nrm = mn;
    if (mn > maxn) { pscale = maxn / mn; nrm = maxn; }
    float yn = fmaxf(nrm, 1e-15f);
    float u = fminf(sc * yn, 1.f - 1e-5f);
    float art = 0.5f * __logf((1.f + u) / (1.f - u));
    float lf = art / (yn * sc);

    float alpha = 1.f / (1.f + __expf(-(ap + __ldg(walpha_b))));
    float coef = alpha * pscale * lf * inv_den;
    float va = ca * coef, vb = cb * coef;

    if (valid) {
        float* dst = d_agg + (size_t)o * 64;
        float p0, p1, p2, p3;
        p0 = va * x0a.x + vb * y0a.x; p1 = va * x0a.y + vb * y0a.y;
        p2 = va * x0a.z + vb * y0a.z; p3 = va * x0a.w + vb * y0a.w;
        asm volatile("red.global.add.v4.f32 [%0], {%1, %2, %3, %4};"
                     :: "l"(dst + 4 * l4), "f"(p0), "f"(p1), "f"(p2), "f"(p3) : "memory");
        p0 = va * x0b.x + vb * y0b.x; p1 = va * x0b.y + vb * y0b.y;
        p2 = va * x0b.z + vb * y0b.z; p3 = va * x0b.w + vb * y0b.w;
        asm volatile("red.global.add.v4.f32 [%0], {%1, %2, %3, %4};"
                     :: "l"(dst + 32 + 4 * l4), "f"(p0), "f"(p1), "f"(p2), "f"(p3) : "memory");
        p0 = va * x1a.x + vb * y1a.x; p1 = va * x1a.y + vb * y1a.y;
        p2 = va * x1a.z + vb * y1a.z; p3 = va * x1a.w + vb * y1a.w;
        asm volatile("red.global.add.v4.f32 [%0], {%1, %2, %3, %4};"
                     :: "l"(dst + 16 + 4 * l4), "f"(p0), "f"(p1), "f"(p2), "f"(p3) : "memory");
        p0 = va * x1b.x + vb * y1b.x; p1 = va * x1b.y + vb * y1b.y;
        p2 = va * x1b.z + vb * y1b.z; p3 = va * x1b.w + vb * y1b.w;
        asm volatile("red.global.add.v4.f32 [%0], {%1, %2, %3, %4};"
                     :: "l"(dst + 48 + 4 * l4), "f"(p0), "f"(p1), "f"(p2), "f"(p3) : "memory");
    }
}

// ---------------------------------------------------------------------------
// K4: out = agg @ Wh via tf32 2-term split (Ah+Al)·Bh. W pre-converted to
// tf32 in static shared at load; mainloop = pure LDS + 2 mma (no cvt).
// 128 threads (4 warps), 64 rows per block.
// ---------------------------------------------------------------------------
__global__ void __launch_bounds__(128)
out_gemm(const float* __restrict__ Wh, float* __restrict__ out, int nNode) {
    __shared__ float shA[64][68];      // 17.4 KB
    __shared__ unsigned sW[64][72];    // 18.4 KB (tf32 of Wh)
    int t = threadIdx.x;
    int base = blockIdx.x * 64;

#pragma unroll
    for (int i = t; i < 4096; i += 128) sW[i >> 6][i & 63] = tf32_rn(Wh[i]);
#pragma unroll
    for (int i = t; i < 4096; i += 128) {
        int rr = i >> 6, cc = i & 63;
        int n = base + rr;
        shA[rr][cc] = (n < nNode) ? d_agg[(size_t)n * 64 + cc] : 0.f;
    }
    __syncthreads();

    int warp = t >> 5, lane = t & 31;
    int rowB = warp * 16;
    int qr = lane >> 2, tg = lane & 3;

    unsigned ah4[8][4], al4[8][4];
#pragma unroll
    for (int k = 0; k < 8; k++) {
        int col = k * 8 + tg;
#pragma unroll
        for (int r = 0; r < 4; r++) {
            int row = rowB + qr + ((r & 1) ? 8 : 0);
            int cc = col + ((r >= 2) ? 4 : 0);
            float v = shA[row][cc];
            unsigned h = tf32_rn(v);
            ah4[k][r] = h;
            al4[k][r] = tf32_rn(v - __uint_as_float(h));
        }
    }

#pragma unroll
    for (int n8 = 0; n8 < 8; n8++) {
        float acc[4] = {0.f, 0.f, 0.f, 0.f};
#pragma unroll
        for (int k = 0; k < 8; k++) {
            unsigned bh[2];
            bh[0] = sW[k * 8 + tg][n8 * 8 + qr];
            bh[1] = sW[k * 8 + tg + 4][n8 * 8 + qr];
            mma_tf32(acc, ah4[k], bh);
            mma_tf32(acc, al4[k], bh);
        }
        int j = n8 * 8 + 2 * tg;
        int n0 = base + rowB + qr, n1 = n0 + 8;
        if (n0 < nNode) *(float2*)&out[(size_t)n0 * 64 + j] = make_float2(acc[0], acc[1]);
        if (n1 < nNode) *(float2*)&out[(size_t)n1 * 64 + j] = make_float2(acc[2], acc[3]);
    }
}

// ---------------------------------------------------------------------------
extern "C" void kernel_launch(void* const* d_in, const int* in_sizes, int n_in,
                              void* d_out, int out_size) {
    const float* hidden   = (const float*)d_in[0];
    const float* rela     = (const float*)d_in[1];
    const float* Ws       = (const float*)d_in[2];
    const float* Wr       = (const float*)d_in[3];
    const float* Wqr      = (const float*)d_in[4];
    const float* Wqr_b    = (const float*)d_in[5];
    const float* walpha_w = (const float*)d_in[6];
    const float* walpha_b = (const float*)d_in[7];
    const float* Wh       = (const float*)d_in[8];
    const float* curv     = (const float*)d_in[9];
    const int* sub = (const int*)d_in[10];
    const int* rel = (const int*)d_in[11];
    const int* obj = (const int*)d_in[12];
    const int* qr  = (const int*)d_in[13];
    float* out = (float*)d_out;

    int nNode = in_sizes[0] / DIM;
    int nRel  = in_sizes[1] / DIM;
    int E     = in_sizes[10];

    build_rel<<<(nRel + 7) / 8, 256>>>(rela, Wr, Wqr, Wqr_b, curv, nRel);
    build_node<<<(nNode + 63) / 64, 128>>>(hidden, Ws, curv, nNode);
    int blocks = (E + 63) / 64;   // 8 edges/warp, 8 warps/block
    edge_kernel<<<blocks, 256>>>(sub, rel, obj, qr, walpha_w, walpha_b, curv, E);
    out_gemm<<<(nNode + 63) / 64, 128>>>(Wh, out, nNode);
}

// round 17
// speedup vs baseline: 1.2723x; 1.0227x over previous
#include <cuda_runtime.h>
#include <cuda_fp16.h>
#include <math.h>

#define MAX_NODE 200000
#define MAX_REL  401
#define DIM      64
#define NODE_STRIDE 64   // floats per node row: 256B = [x fp16 64 | A fp16 64], permuted
#define REL_STRIDE  96   // floats per rel row: 384B = [y fp16 | B fp16 | C fp16], permuted

// Scratch:
//   node table: [expmap0(h): 64 fp16 | A=h@Ws: 64 fp16], both PERMUTED (~51 MB)
//     permutation: 16B slot p of a section = dims {4p..4p+3, 32+4p..32+4p+3}
//   rel  table: [expmap0(r) | r@Wr | r@Wqr+b], fp16, same permuted slots (~150 KB)
//   agg buffer: scatter-sum destination fp32 (~51 MB)
__device__ float d_nodeT[(size_t)MAX_NODE * NODE_STRIDE];
__device__ float d_relT[(size_t)MAX_REL * REL_STRIDE];
__device__ float d_agg[(size_t)MAX_NODE * 64];

// ---- tf32 mma helpers -----------------------------------------------------
__device__ __forceinline__ unsigned tf32_rn(float f) {
    unsigned r;
    asm("cvt.rna.tf32.f32 %0, %1;" : "=r"(r) : "f"(f));
    return r;
}
__device__ __forceinline__ void mma_tf32(float d[4], const unsigned a[4], const unsigned b[2]) {
    asm("mma.sync.aligned.m16n8k8.row.col.f32.tf32.tf32.f32 "
        "{%0,%1,%2,%3}, {%4,%5,%6,%7}, {%8,%9}, {%0,%1,%2,%3};"
        : "+f"(d[0]), "+f"(d[1]), "+f"(d[2]), "+f"(d[3])
        : "r"(a[0]), "r"(a[1]), "r"(a[2]), "r"(a[3]), "r"(b[0]), "r"(b[1]));
}
// byte offset of fp16 column j within a permuted 128B section (j even)
__device__ __forceinline__ int perm_off(int j) {
    return (j < 32) ? ((j >> 2) * 16 + (j & 3) * 2)
                    : (((j - 32) >> 2) * 16 + 8 + ((j - 32) & 3) * 2);
}
// unpack a 16B slot (8 fp16) into two float4s (first/second half of slot)
__device__ __forceinline__ void unp8(uint4 u, float4& lo, float4& hi) {
    __half2* h = (__half2*)&u;
    float2 p0 = __half22float2(h[0]);
    float2 p1 = __half22float2(h[1]);
    float2 p2 = __half22float2(h[2]);
    float2 p3 = __half22float2(h[3]);
    lo = make_float4(p0.x, p0.y, p1.x, p1.y);
    hi = make_float4(p2.x, p2.y, p3.x, p3.y);
}
__device__ __forceinline__ float dot4(float4 a, float4 b) {
    return a.x * b.x + a.y * b.y + a.z * b.z + a.w * b.w;
}

// ---------------------------------------------------------------------------
// K1: relation table (fp16 permuted). One warp per relation; lane l owns
// dims 2l, 2l+1.
// ---------------------------------------------------------------------------
__global__ void build_rel(const float* __restrict__ rela,
                          const float* __restrict__ Wr,
                          const float* __restrict__ Wqr,
                          const float* __restrict__ Wqr_b,
                          const float* __restrict__ curv, int nRel) {
    __shared__ float sh[8][64];
    int warp = threadIdx.x >> 5, lane = threadIdx.x & 31;
    int r = blockIdx.x * 8 + warp;
    if (r >= nRel) return;
    float c = fmaxf(curv[0], 1e-6f);
    float sc = sqrtf(c);

    float2 h = ((const float2*)(rela + (size_t)r * 64))[lane];
    sh[warp][2 * lane] = h.x;
    sh[warp][2 * lane + 1] = h.y;

    float n2 = h.x * h.x + h.y * h.y;
#pragma unroll
    for (int off = 16; off; off >>= 1) n2 += __shfl_xor_sync(~0u, n2, off);
    float un = fmaxf(sqrtf(n2), 1e-15f);
    float arg = fminf(sc * un, 15.0f);
    float t = tanhf(arg);
    float gs = t / (sc * un);
    float gn = fmaxf(un * gs, 1e-15f);
    float maxn = 0.996f / sc;
    if (gn > maxn) gs *= maxn / gn;
    __syncwarp();

    float b0 = 0.f, b1 = 0.f;
    float c0 = Wqr_b[2 * lane], c1 = Wqr_b[2 * lane + 1];
    for (int i = 0; i < 64; i++) {
        float hi = sh[warp][i];
        float2 wr = ((const float2*)(Wr + (size_t)i * 64))[lane];
        float2 wq = ((const float2*)(Wqr + (size_t)i * 64))[lane];
        b0 = fmaf(hi, wr.x, b0); b1 = fmaf(hi, wr.y, b1);
        c0 = fmaf(hi, wq.x, c0); c1 = fmaf(hi, wq.y, c1);
    }
    char* base = (char*)(d_relT + (size_t)r * REL_STRIDE);
    int off = perm_off(2 * lane);
    *(__half2*)(base + off)       = __floats2half2_rn(h.x * gs, h.y * gs);
    *(__half2*)(base + 128 + off) = __floats2half2_rn(b0, b1);
    *(__half2*)(base + 256 + off) = __floats2half2_rn(c0, c1);
}

// ---------------------------------------------------------------------------
// K2: node table + agg zeroing. 128 threads (4 warps), 64 nodes per block.
// A = h@Ws via single-pass tf32 mma; Ws PRE-CONVERTED to tf32 in shared
// (no in-mainloop cvt). fp16 PERMUTED stores for x and A sections.
// ---------------------------------------------------------------------------
__global__ void __launch_bounds__(128)
build_node(const float* __restrict__ hidden,
           const float* __restrict__ Ws,
           const float* __restrict__ curv, int nNode) {
    __shared__ float shA[64][68];      // hidden rows, pad 68
    __shared__ unsigned shW[64][72];   // Ws as tf32, pad 72
    int t = threadIdx.x;            // 0..127
    int base = blockIdx.x * 64;
    float c = fmaxf(curv[0], 1e-6f);
    float sc = sqrtf(c);

    // zero agg rows for these 64 nodes
    float4 z = make_float4(0.f, 0.f, 0.f, 0.f);
#pragma unroll
    for (int i = t; i < 1024; i += 128) {
        int n = base + (i >> 4);
        if (n < nNode) ((float4*)(d_agg + (size_t)n * 64))[i & 15] = z;
    }
#pragma unroll
    for (int i = t; i < 4096; i += 128) shW[i >> 6][i & 63] = tf32_rn(Ws[i]);
#pragma unroll
    for (int i = t; i < 4096; i += 128) {
        int rr = i >> 6, cc = i & 63;
        int n = base + rr;
        shA[rr][cc] = (n < nNode) ? hidden[(size_t)n * 64 + cc] : 0.f;
    }
    __syncthreads();

    int warp = t >> 5, lane = t & 31;
    int rowB = warp * 16;
    int qr = lane >> 2, tg = lane & 3;

    unsigned av[8][4];
#pragma unroll
    for (int k = 0; k < 8; k++) {
        int col = k * 8 + tg;
        av[k][0] = tf32_rn(shA[rowB + qr][col]);
        av[k][1] = tf32_rn(shA[rowB + qr + 8][col]);
        av[k][2] = tf32_rn(shA[rowB + qr][col + 4]);
        av[k][3] = tf32_rn(shA[rowB + qr + 8][col + 4]);
    }

#pragma unroll
    for (int n8 = 0; n8 < 8; n8++) {
        float acc[4] = {0.f, 0.f, 0.f, 0.f};
#pragma unroll
        for (int k = 0; k < 8; k++) {
            unsigned bv[2];
            bv[0] = shW[k * 8 + tg][n8 * 8 + qr];
            bv[1] = shW[k * 8 + tg + 4][n8 * 8 + qr];
            mma_tf32(acc, av[k], bv);
        }
        int j = n8 * 8 + 2 * tg;                   // even column
        int off = 128 + perm_off(j);               // A section at byte 128
        int n0 = base + rowB + qr, n1 = n0 + 8;
        if (n0 < nNode) {
            __half2 hh = __floats2half2_rn(acc[0], acc[1]);
            *(__half2*)((char*)(d_nodeT + (size_t)n0 * NODE_STRIDE) + off) = hh;
        }
        if (n1 < nNode) {
            __half2 hh = __floats2half2_rn(acc[2], acc[3]);
            *(__half2*)((char*)(d_nodeT + (size_t)n1 * NODE_STRIDE) + off) = hh;
        }
    }

    // expmap0 per node (fp32 math, fp16 permuted store); warp w: nodes w, w+4, ...
    for (int k = warp; k < 64; k += 4) {
        int n = base + k;
        if (n >= nNode) continue;
        float h0 = shA[k][2 * lane], h1 = shA[k][2 * lane + 1];
        float n2 = h0 * h0 + h1 * h1;
#pragma unroll
        for (int off = 16; off; off >>= 1) n2 += __shfl_xor_sync(~0u, n2, off);
        float un = fmaxf(sqrtf(n2), 1e-15f);
        float arg = fminf(sc * un, 15.0f);
        float tt = tanhf(arg);
        float gs = tt / (sc * un);
        float gn = fmaxf(un * gs, 1e-15f);
        float maxn = 0.996f / sc;
        if (gn > maxn) gs *= maxn / gn;
        int off = perm_off(2 * lane);              // x section at byte 0
        __half2 hh = __floats2half2_rn(h0 * gs, h1 * gs);
        *(__half2*)((char*)(d_nodeT + (size_t)n * NODE_STRIDE) + off) = hh;
    }
}

// ---------------------------------------------------------------------------
// K3: edge kernel. 8 edges per warp; 4 lanes per edge; lane owns slots
// {l4, l4+4} = dims {4l4.., 32+4l4.., 16+4l4.., 48+4l4..} (16 dims).
// All tables fp16 permuted. Scatter: 4x red.global.add.v4.f32. (unchanged)
// ---------------------------------------------------------------------------
__global__ void __launch_bounds__(256)
edge_kernel(const int* __restrict__ sub, const int* __restrict__ rel,
            const int* __restrict__ obj, const int* __restrict__ qr,
            const float* __restrict__ walpha_w,
            const float* __restrict__ walpha_b,
            const float* __restrict__ curv, int E) {
    int lane = threadIdx.x & 31;
    int g    = lane >> 2;   // edge group 0..7
    int l4   = lane & 3;    // lane within 4-lane edge group
    int warpId = (blockIdx.x * blockDim.x + threadIdx.x) >> 5;
    long long e = (long long)warpId * 8 + g;
    bool valid = (e < E);
    int ei = valid ? (int)e : 0;

    float c = fmaxf(__ldg(curv), 1e-6f);
    float sc = sqrtf(c);

    int s = __ldg(sub + ei);
    int r = __ldg(rel + ei);
    int o = __ldg(obj + ei);
    int q = __ldg(qr + ei);

    const uint4* nrow = (const uint4*)(d_nodeT + (size_t)s * NODE_STRIDE);
    const uint4* rrow = (const uint4*)(d_relT + (size_t)r * REL_STRIDE);
    const uint4* qrow = (const uint4*)(d_relT + (size_t)q * REL_STRIDE);
    const float4* w4  = (const float4*)walpha_w;

    uint4 xu0 = nrow[l4],      xu1 = nrow[4 + l4];    // x slots l4, l4+4
    uint4 au0 = nrow[8 + l4],  au1 = nrow[12 + l4];   // A slots
    uint4 yu0 = rrow[l4],      yu1 = rrow[4 + l4];    // y slots
    uint4 bu0 = rrow[8 + l4],  bu1 = rrow[12 + l4];   // B slots
    uint4 cu0 = qrow[16 + l4], cu1 = qrow[20 + l4];   // C slots
    float4 wA0 = w4[l4],       wA1 = w4[8 + l4];      // w dims of slot l4
    float4 wB0 = w4[4 + l4],   wB1 = w4[12 + l4];     // w dims of slot l4+4

    float4 x0a, x0b, x1a, x1b, y0a, y0b, y1a, y1b;
    unp8(xu0, x0a, x0b); unp8(xu1, x1a, x1b);
    unp8(yu0, y0a, y0b); unp8(yu1, y1a, y1b);

    float x2 = dot4(x0a, x0a) + dot4(x0b, x0b) + dot4(x1a, x1a) + dot4(x1b, x1b);
    float y2 = dot4(y0a, y0a) + dot4(y0b, y0b) + dot4(y1a, y1a) + dot4(y1b, y1b);
    float xy = dot4(x0a, y0a) + dot4(x0b, y0b) + dot4(x1a, y1a) + dot4(x1b, y1b);

    float ap;
    {
        float4 aa, ab, ba, bb, ca, cb;
        unp8(au0, aa, ab); unp8(bu0, ba, bb); unp8(cu0, ca, cb);
        ap = fmaxf(aa.x + ba.x + ca.x, 0.f) * wA0.x
           + fmaxf(aa.y + ba.y + ca.y, 0.f) * wA0.y
           + fmaxf(aa.z + ba.z + ca.z, 0.f) * wA0.z
           + fmaxf(aa.w + ba.w + ca.w, 0.f) * wA0.w
           + fmaxf(ab.x + bb.x + cb.x, 0.f) * wA1.x
           + fmaxf(ab.y + bb.y + cb.y, 0.f) * wA1.y
           + fmaxf(ab.z + bb.z + cb.z, 0.f) * wA1.z
           + fmaxf(ab.w + bb.w + cb.w, 0.f) * wA1.w;
        unp8(au1, aa, ab); unp8(bu1, ba, bb); unp8(cu1, ca, cb);
        ap += fmaxf(aa.x + ba.x + ca.x, 0.f) * wB0.x
            + fmaxf(aa.y + ba.y + ca.y, 0.f) * wB0.y
            + fmaxf(aa.z + ba.z + ca.z, 0.f) * wB0.z
            + fmaxf(aa.w + ba.w + ca.w, 0.f) * wB0.w
            + fmaxf(ab.x + bb.x + cb.x, 0.f) * wB1.x
            + fmaxf(ab.y + bb.y + cb.y, 0.f) * wB1.y
            + fmaxf(ab.z + bb.z + cb.z, 0.f) * wB1.z
            + fmaxf(ab.w + bb.w + cb.w, 0.f) * wB1.w;
    }

    // reduce within the 4-lane group (xor offsets 2,1 stay inside group)
#pragma unroll
    for (int off = 2; off; off >>= 1) {
        x2 += __shfl_xor_sync(~0u, x2, off);
        y2 += __shfl_xor_sync(~0u, y2, off);
        xy += __shfl_xor_sync(~0u, xy, off);
        ap += __shfl_xor_sync(~0u, ap, off);
    }

    float ca = 1.f + 2.f * c * xy + c * y2;
    float cb = 1.f - c * x2;
    float den = fmaxf(1.f + 2.f * c * xy + c * c * x2 * y2, 1e-15f);
    float inv_den = 1.f / den;
    float m2 = ca * ca * x2 + 2.f * ca * cb * xy + cb * cb * y2;
    float mn = sqrtf(m2) * inv_den;

    float maxn = 0.996f / sc;
    float pscale = 1.f, nrm = mn;
    if (mn > maxn) { pscale = maxn / mn; nrm = maxn; }
    float yn = fmaxf(nrm, 1e-15f);
    float u = fminf(sc * yn, 1.f - 1e-5f);
    float art = 0.5f * __logf((1.f + u) / (1.f - u));
    float lf = art / (yn * sc);

    float alpha = 1.f / (1.f + __expf(-(ap + __ldg(walpha_b))));
    float coef = alpha * pscale * lf * inv_den;
    float va = ca * coef, vb = cb * coef;

    if (valid) {
        float* dst = d_agg + (size_t)o * 64;
        float p0, p1, p2, p3;
        p0 = va * x0a.x + vb * y0a.x; p1 = va * x0a.y + vb * y0a.y;
        p2 = va * x0a.z + vb * y0a.z; p3 = va * x0a.w + vb * y0a.w;
        asm volatile("red.global.add.v4.f32 [%0], {%1, %2, %3, %4};"
                     :: "l"(dst + 4 * l4), "f"(p0), "f"(p1), "f"(p2), "f"(p3) : "memory");
        p0 = va * x0b.x + vb * y0b.x; p1 = va * x0b.y + vb * y0b.y;
        p2 = va * x0b.z + vb * y0b.z; p3 = va * x0b.w + vb * y0b.w;
        asm volatile("red.global.add.v4.f32 [%0], {%1, %2, %3, %4};"
                     :: "l"(dst + 32 + 4 * l4), "f"(p0), "f"(p1), "f"(p2), "f"(p3) : "memory");
        p0 = va * x1a.x + vb * y1a.x; p1 = va * x1a.y + vb * y1a.y;
        p2 = va * x1a.z + vb * y1a.z; p3 = va * x1a.w + vb * y1a.w;
        asm volatile("red.global.add.v4.f32 [%0], {%1, %2, %3, %4};"
                     :: "l"(dst + 16 + 4 * l4), "f"(p0), "f"(p1), "f"(p2), "f"(p3) : "memory");
        p0 = va * x1b.x + vb * y1b.x; p1 = va * x1b.y + vb * y1b.y;
        p2 = va * x1b.z + vb * y1b.z; p3 = va * x1b.w + vb * y1b.w;
        asm volatile("red.global.add.v4.f32 [%0], {%1, %2, %3, %4};"
                     :: "l"(dst + 48 + 4 * l4), "f"(p0), "f"(p1), "f"(p2), "f"(p3) : "memory");
    }
}

// ---------------------------------------------------------------------------
// K4: out = agg @ Wh via tf32 2-term split (Ah+Al)·Bh. W pre-converted to
// tf32 in shared; A fragments loaded + split INSIDE the k-loop (8 live regs
// instead of 64 hoisted -> regs ~64, occupancy 2x). acc[8][4] = 32 regs.
// 128 threads (4 warps), 64 rows per block.
// ---------------------------------------------------------------------------
__global__ void __launch_bounds__(128)
out_gemm(const float* __restrict__ Wh, float* __restrict__ out, int nNode) {
    __shared__ float shA[64][68];      // 17.4 KB
    __shared__ unsigned sW[64][72];    // 18.4 KB (tf32 of Wh)
    int t = threadIdx.x;
    int base = blockIdx.x * 64;

#pragma unroll
    for (int i = t; i < 4096; i += 128) sW[i >> 6][i & 63] = tf32_rn(Wh[i]);
#pragma unroll
    for (int i = t; i < 4096; i += 128) {
        int rr = i >> 6, cc = i & 63;
        int n = base + rr;
        shA[rr][cc] = (n < nNode) ? d_agg[(size_t)n * 64 + cc] : 0.f;
    }
    __syncthreads();

    int warp = t >> 5, lane = t & 31;
    int rowB = warp * 16;
    int qr = lane >> 2, tg = lane & 3;

    float acc[8][4];
#pragma unroll
    for (int n8 = 0; n8 < 8; n8++)
#pragma unroll
        for (int i = 0; i < 4; i++) acc[n8][i] = 0.f;

#pragma unroll
    for (int k = 0; k < 8; k++) {
        int col = k * 8 + tg;
        unsigned ah[4], al[4];
#pragma unroll
        for (int r = 0; r < 4; r++) {
            int row = rowB + qr + ((r & 1) ? 8 : 0);
            int cc = col + ((r >= 2) ? 4 : 0);
            float v = shA[row][cc];
            unsigned h = tf32_rn(v);
            ah[r] = h;
            al[r] = tf32_rn(v - __uint_as_float(h));
        }
#pragma unroll
        for (int n8 = 0; n8 < 8; n8++) {
            unsigned bh[2];
            bh[0] = sW[k * 8 + tg][n8 * 8 + qr];
            bh[1] = sW[k * 8 + tg + 4][n8 * 8 + qr];
            mma_tf32(acc[n8], ah, bh);
            mma_tf32(acc[n8], al, bh);
        }
    }

#pragma unroll
    for (int n8 = 0; n8 < 8; n8++) {
        int j = n8 * 8 + 2 * tg;
        int n0 = base + rowB + qr, n1 = n0 + 8;
        if (n0 < nNode) *(float2*)&out[(size_t)n0 * 64 + j] = make_float2(acc[n8][0], acc[n8][1]);
        if (n1 < nNode) *(float2*)&out[(size_t)n1 * 64 + j] = make_float2(acc[n8][2], acc[n8][3]);
    }
}

// ---------------------------------------------------------------------------
extern "C" void kernel_launch(void* const* d_in, const int* in_sizes, int n_in,
                              void* d_out, int out_size) {
    const float* hidden   = (const float*)d_in[0];
    const float* rela     = (const float*)d_in[1];
    const float* Ws       = (const float*)d_in[2];
    const float* Wr       = (const float*)d_in[3];
    const float* Wqr      = (const float*)d_in[4];
    const float* Wqr_b    = (const float*)d_in[5];
    const float* walpha_w = (const float*)d_in[6];
    const float* walpha_b = (const float*)d_in[7];
    const float* Wh       = (const float*)d_in[8];
    const float* curv     = (const float*)d_in[9];
    const int* sub = (const int*)d_in[10];
    const int* rel = (const int*)d_in[11];
    const int* obj = (const int*)d_in[12];
    const int* qr  = (const int*)d_in[13];
    float* out = (float*)d_out;

    int nNode = in_sizes[0] / DIM;
    int nRel  = in_sizes[1] / DIM;
    int E     = in_sizes[10];

    build_rel<<<(nRel + 7) / 8, 256>>>(rela, Wr, Wqr, Wqr_b, curv, nRel);
    build_node<<<(nNode + 63) / 64, 128>>>(hidden, Ws, curv, nNode);
    int blocks = (E + 63) / 64;   // 8 edges/warp, 8 warps/block
    edge_kernel<<<blocks, 256>>>(sub, rel, obj, qr, walpha_w, walpha_b, curv, E);
    out_gemm<<<(nNode + 63) / 64, 128>>>(Wh, out, nNode);
}